// round 3
// baseline (speedup 1.0000x reference)
#include <cuda_runtime.h>
#include <cuda_bf16.h>
#include <math.h>
#include <float.h>

#define Bb   2
#define Tt   1024
#define Cc   768
#define Hh   12
#define Dd   64
#define HID  3072
#define Mrows (Bb*Tt)          // 2048

// ---------------- scratch (static device allocations; no cudaMalloc) ----------
__device__ float g_h   [Mrows*Cc];       // LN1 output
__device__ float g_qkv [Mrows*3*Cc];     // qkv
__device__ float g_o   [Mrows*Cc];       // attention output
__device__ float g_x1  [Mrows*Cc];       // x + attn-proj
__device__ float g_h2  [Mrows*Cc];       // LN2 output
__device__ float g_gate[Mrows*HID];      // fc output ("gate" in ref)
__device__ float g_u   [Mrows*HID];      // gelu(w_gate out)*gate
__device__ float g_rn  [Mrows];          // row norms (reused per stage)
__device__ float g_cn  [HID];            // col norms (reused per stage)

// ---------------- helpers ------------------------------------------------------
__device__ __forceinline__ float blockReduceSum(float v) {
    __shared__ float sh[8];
    int lane = threadIdx.x & 31, w = threadIdx.x >> 5;
    #pragma unroll
    for (int o = 16; o; o >>= 1) v += __shfl_xor_sync(0xffffffffu, v, o);
    __syncthreads();               // protect sh across repeated calls
    if (lane == 0) sh[w] = v;
    __syncthreads();
    return sh[0]+sh[1]+sh[2]+sh[3]+sh[4]+sh[5]+sh[6]+sh[7];
}

__device__ __forceinline__ float gelu_tanh(float x) {
    float x3 = x * x * x;
    float t  = tanhf(0.7978845608028654f * (x + 0.044715f * x3));
    return 0.5f * x * (1.0f + t);
}

// ---------------- LayerNorm + rownorm ------------------------------------------
__global__ __launch_bounds__(256)
void ln_kernel(const float* __restrict__ x, const float* __restrict__ sc,
               float* __restrict__ h, float* __restrict__ rn)
{
    int row = blockIdx.x;
    const float* xr = x + (size_t)row * Cc;
    int t = threadIdx.x;
    float v0 = xr[t], v1 = xr[t+256], v2 = xr[t+512];
    float s  = blockReduceSum(v0+v1+v2);
    float ss = blockReduceSum(v0*v0+v1*v1+v2*v2);
    float mu  = s  * (1.0f/768.0f);
    float var = ss * (1.0f/768.0f) - mu*mu;
    float rs  = rsqrtf(var + 1e-6f);
    float o0 = (v0-mu)*rs*sc[t];
    float o1 = (v1-mu)*rs*sc[t+256];
    float o2 = (v2-mu)*rs*sc[t+512];
    float* hr = h + (size_t)row * Cc;
    hr[t] = o0; hr[t+256] = o1; hr[t+512] = o2;
    float hn = blockReduceSum(o0*o0+o1*o1+o2*o2);
    if (t == 0) rn[row] = hn;
}

// ---------------- generic rownorm ----------------------------------------------
__global__ __launch_bounds__(256)
void rownorm_kernel(const float* __restrict__ a, float* __restrict__ rn, int C)
{
    int row = blockIdx.x;
    const float* ar = a + (size_t)row * C;
    float s = 0.f;
    for (int c = threadIdx.x; c < C; c += 256) { float v = ar[c]; s += v*v; }
    s = blockReduceSum(s);
    if (threadIdx.x == 0) rn[row] = s;
}

// ---------------- column norms of W (K x N row-major) ---------------------------
__global__ __launch_bounds__(256)
void colnorm_kernel(const float* __restrict__ W, float* __restrict__ cn, int K, int N)
{
    int n = blockIdx.x * 256 + threadIdx.x;
    if (n >= N) return;
    float s = 0.f;
    for (int k = 0; k < K; k++) { float v = W[(size_t)k * N + n]; s += v*v; }
    cn[n] = s;
}

// ---------------- elementwise "rope" (cos/sin scaling) on q,k -------------------
__global__ __launch_bounds__(256)
void rope_kernel(float* __restrict__ qkv)
{
    int i = blockIdx.x * 256 + threadIdx.x;     // over Mrows*Cc
    if (i >= Mrows * Cc) return;
    int hd  = i % Cc;
    int row = i / Cc;
    int t   = row % Tt;
    int d   = hd & 63;
    int ii  = d & 31;
    float freq = expf((float)(2*ii) * (-logf(10000.0f) / 64.0f));
    float ang  = (float)t * freq;
    float r    = (d < 32) ? cosf(ang) : sinf(ang);
    size_t base = (size_t)row * (3*Cc);
    qkv[base + hd]      *= r;    // q
    qkv[base + Cc + hd] *= r;    // k
}

// ---------------- fp32 SGEMM + yat epilogue -------------------------------------
// C[m,n] = epilogue( sum_k A[m,k]*W[k,n] )
// MODE 0: out = yat            MODE 1: out = extra + yat     MODE 2: out = gelu(yat)*extra
#define BM 128
#define BN 128
#define BK 16

template<int MODE>
__global__ __launch_bounds__(256, 2)
void gemm_yat(const float* __restrict__ A, const float* __restrict__ W,
              float* __restrict__ out,
              const float* __restrict__ rn, const float* __restrict__ cn,
              const float* __restrict__ bias, const float* __restrict__ alphap,
              const float* __restrict__ extra,
              int M, int N, int K)
{
    __shared__ float As[BK*BM];
    __shared__ float Bs[BK*BN];
    int tid = threadIdx.x;
    int m0 = blockIdx.y * BM;
    int n0 = blockIdx.x * BN;

    int arow = tid >> 2;            // 0..63
    int ak   = (tid & 3) * 4;       // 0,4,8,12
    int brow = tid >> 5;            // 0..7
    int bn   = (tid & 31) * 4;      // 0..124

    const float* Ap0 = A + (size_t)(m0 + arow)      * K + ak;
    const float* Ap1 = A + (size_t)(m0 + arow + 64) * K + ak;

    // --- load tile 0 ---
    {
        float4 a0 = *(const float4*)(Ap0);
        float4 a1 = *(const float4*)(Ap1);
        float4 b0 = *(const float4*)(W + (size_t)(brow)     * N + n0 + bn);
        float4 b1 = *(const float4*)(W + (size_t)(brow + 8) * N + n0 + bn);
        As[(ak+0)*BM + arow] = a0.x; As[(ak+1)*BM + arow] = a0.y;
        As[(ak+2)*BM + arow] = a0.z; As[(ak+3)*BM + arow] = a0.w;
        As[(ak+0)*BM + arow+64] = a1.x; As[(ak+1)*BM + arow+64] = a1.y;
        As[(ak+2)*BM + arow+64] = a1.z; As[(ak+3)*BM + arow+64] = a1.w;
        *(float4*)&Bs[brow*BN + bn]     = b0;
        *(float4*)&Bs[(brow+8)*BN + bn] = b1;
    }
    __syncthreads();

    int tm = tid >> 4, tn = tid & 15;
    float acc[8][8];
    #pragma unroll
    for (int i = 0; i < 8; i++)
        #pragma unroll
        for (int j = 0; j < 8; j++) acc[i][j] = 0.f;

    int KT = K >> 4;
    for (int kt = 0; kt < KT; kt++) {
        float4 na0, na1, nb0, nb1;
        if (kt + 1 < KT) {
            int k0 = (kt + 1) * BK;
            na0 = *(const float4*)(Ap0 + k0);
            na1 = *(const float4*)(Ap1 + k0);
            nb0 = *(const float4*)(W + (size_t)(k0 + brow)     * N + n0 + bn);
            nb1 = *(const float4*)(W + (size_t)(k0 + brow + 8) * N + n0 + bn);
        }
        #pragma unroll
        for (int kk = 0; kk < BK; kk++) {
            float4 aA = *(float4*)&As[kk*BM + tm*4];
            float4 aB = *(float4*)&As[kk*BM + 64 + tm*4];
            float4 bA = *(float4*)&Bs[kk*BN + tn*4];
            float4 bB = *(float4*)&Bs[kk*BN + 64 + tn*4];
            float av[8] = {aA.x,aA.y,aA.z,aA.w, aB.x,aB.y,aB.z,aB.w};
            float bv[8] = {bA.x,bA.y,bA.z,bA.w, bB.x,bB.y,bB.z,bB.w};
            #pragma unroll
            for (int i = 0; i < 8; i++)
                #pragma unroll
                for (int j = 0; j < 8; j++)
                    acc[i][j] = fmaf(av[i], bv[j], acc[i][j]);
        }
        __syncthreads();
        if (kt + 1 < KT) {
            As[(ak+0)*BM + arow] = na0.x; As[(ak+1)*BM + arow] = na0.y;
            As[(ak+2)*BM + arow] = na0.z; As[(ak+3)*BM + arow] = na0.w;
            As[(ak+0)*BM + arow+64] = na1.x; As[(ak+1)*BM + arow+64] = na1.y;
            As[(ak+2)*BM + arow+64] = na1.z; As[(ak+3)*BM + arow+64] = na1.w;
            *(float4*)&Bs[brow*BN + bn]     = nb0;
            *(float4*)&Bs[(brow+8)*BN + bn] = nb1;
            __syncthreads();
        }
    }

    // --- yat epilogue ---
    float a0v = alphap[0];
    float sc  = powf(sqrtf((float)N) / log1pf((float)N), a0v);

    #pragma unroll
    for (int i = 0; i < 8; i++) {
        int rloc = (i < 4) ? (tm*4 + i) : (64 + tm*4 + i - 4);
        int m = m0 + rloc;
        float rnv = rn[m];
        #pragma unroll
        for (int jq = 0; jq < 2; jq++) {
            int cbase = n0 + jq*64 + tn*4;
            float4 res;
            float* rp = (float*)&res;
            #pragma unroll
            for (int e = 0; e < 4; e++) {
                int n = cbase + e;
                float y = acc[i][jq*4 + e];
                float dd = rnv + cn[n] - 2.0f*y + 1e-6f;
                float v = (y*y/dd + bias[n]) * sc;
                if (MODE == 1) v = extra[(size_t)m*N + n] + v;
                if (MODE == 2) v = gelu_tanh(v) * extra[(size_t)m*N + n];
                rp[e] = v;
            }
            *(float4*)(out + (size_t)m*N + cbase) = res;
        }
    }
}

// ---------------- fp32 flash attention (causal, BM=BN=64, D=64) -----------------
__global__ __launch_bounds__(256)
void flash_attn(const float* __restrict__ qkv, float* __restrict__ o)
{
    __shared__ float Qs[64*64];   // [d][row]
    __shared__ float KPs[64*64];  // K: [d][col]  then reused as P: [j][row]
    __shared__ float Vs[64*64];   // [j][d]

    int tid = threadIdx.x;
    int qt = blockIdx.x, h = blockIdx.y, b = blockIdx.z;
    int t0 = qt * 64;
    int ty = tid >> 4, tx = tid & 15;

    // load Q (transposed into [d][row])
    {
        int r = tid >> 2, dc = (tid & 3) * 16;
        const float* qp = qkv + ((size_t)(b*Tt + t0 + r) * (3*Cc)) + h*64 + dc;
        #pragma unroll
        for (int j = 0; j < 4; j++) {
            float4 v = *(const float4*)(qp + j*4);
            int d = dc + j*4;
            Qs[(d+0)*64 + r] = v.x; Qs[(d+1)*64 + r] = v.y;
            Qs[(d+2)*64 + r] = v.z; Qs[(d+3)*64 + r] = v.w;
        }
    }

    float mrun[4], lrun[4], acc[4][4];
    #pragma unroll
    for (int a = 0; a < 4; a++) {
        mrun[a] = -1e30f; lrun[a] = 0.f;
        #pragma unroll
        for (int c = 0; c < 4; c++) acc[a][c] = 0.f;
    }

    int nTiles = qt + 1;
    for (int jt = 0; jt < nTiles; jt++) {
        int j0 = jt * 64;
        __syncthreads();   // prev-iter consumers done before overwrite
        {
            int r = tid >> 2, dc = (tid & 3) * 16;
            const float* kp = qkv + ((size_t)(b*Tt + j0 + r) * (3*Cc)) + Cc + h*64 + dc;
            const float* vp = kp + Cc;
            #pragma unroll
            for (int j = 0; j < 4; j++) {
                float4 v = *(const float4*)(kp + j*4);
                int d = dc + j*4;
                KPs[(d+0)*64 + r] = v.x; KPs[(d+1)*64 + r] = v.y;
                KPs[(d+2)*64 + r] = v.z; KPs[(d+3)*64 + r] = v.w;
            }
            #pragma unroll
            for (int j = 0; j < 4; j++)
                *(float4*)&Vs[r*64 + dc + j*4] = *(const float4*)(vp + j*4);
        }
        __syncthreads();

        // S = Q K^T
        float s[4][4];
        #pragma unroll
        for (int a = 0; a < 4; a++)
            #pragma unroll
            for (int c = 0; c < 4; c++) s[a][c] = 0.f;
        #pragma unroll 8
        for (int d = 0; d < 64; d++) {
            float4 qf = *(float4*)&Qs[d*64 + ty*4];
            float4 kf = *(float4*)&KPs[d*64 + tx*4];
            float qv[4] = {qf.x,qf.y,qf.z,qf.w};
            float kv[4] = {kf.x,kf.y,kf.z,kf.w};
            #pragma unroll
            for (int a = 0; a < 4; a++)
                #pragma unroll
                for (int c = 0; c < 4; c++)
                    s[a][c] = fmaf(qv[a], kv[c], s[a][c]);
        }

        // online softmax update
        float p[4][4];
        #pragma unroll
        for (int a = 0; a < 4; a++) {
            int row = t0 + ty*4 + a;
            float mx = -1e30f;
            #pragma unroll
            for (int c = 0; c < 4; c++) {
                float sv = s[a][c] * 0.125f;
                int col = j0 + tx*4 + c;
                if (col > row) sv = -3.4028235e38f;
                s[a][c] = sv;
                mx = fmaxf(mx, sv);
            }
            #pragma unroll
            for (int off = 8; off; off >>= 1)
                mx = fmaxf(mx, __shfl_xor_sync(0xffffffffu, mx, off));
            float mn = fmaxf(mrun[a], mx);
            float corr = expf(mrun[a] - mn);
            mrun[a] = mn;
            float ls = 0.f;
            #pragma unroll
            for (int c = 0; c < 4; c++) {
                float pv = expf(s[a][c] - mn);
                p[a][c] = pv; ls += pv;
            }
            #pragma unroll
            for (int off = 8; off; off >>= 1)
                ls += __shfl_xor_sync(0xffffffffu, ls, off);
            lrun[a] = lrun[a] * corr + ls;
            #pragma unroll
            for (int c = 0; c < 4; c++) acc[a][c] *= corr;
        }

        __syncthreads();   // everyone done reading KPs (K)
        #pragma unroll
        for (int a = 0; a < 4; a++)
            #pragma unroll
            for (int c = 0; c < 4; c++)
                KPs[(tx*4 + c)*64 + ty*4 + a] = p[a][c];   // P: [j][row]
        __syncthreads();

        // O += P V
        #pragma unroll 8
        for (int j = 0; j < 64; j++) {
            float4 pf = *(float4*)&KPs[j*64 + ty*4];
            float4 vf = *(float4*)&Vs[j*64 + tx*4];
            float pv[4] = {pf.x,pf.y,pf.z,pf.w};
            float vv[4] = {vf.x,vf.y,vf.z,vf.w};
            #pragma unroll
            for (int a = 0; a < 4; a++)
                #pragma unroll
                for (int c = 0; c < 4; c++)
                    acc[a][c] = fmaf(pv[a], vv[c], acc[a][c]);
        }
    }

    #pragma unroll
    for (int a = 0; a < 4; a++) {
        int row = t0 + ty*4 + a;
        float inv = 1.0f / lrun[a];
        float4 ov = make_float4(acc[a][0]*inv, acc[a][1]*inv, acc[a][2]*inv, acc[a][3]*inv);
        *(float4*)(o + (size_t)(b*Tt + row)*Cc + h*64 + tx*4) = ov;
    }
}

// ---------------- launch --------------------------------------------------------
extern "C" void kernel_launch(void* const* d_in, const int* in_sizes, int n_in,
                              void* d_out, int out_size)
{
    (void)in_sizes; (void)n_in; (void)out_size;
    const float* x      = (const float*)d_in[0];
    // d_in[1] = mask (always causal tril; handled analytically)
    const float* ln1    = (const float*)d_in[2];
    const float* w_qkv  = (const float*)d_in[3];
    const float* b_qkv  = (const float*)d_in[4];
    const float* a_qkv  = (const float*)d_in[5];
    const float* w_ao   = (const float*)d_in[6];
    const float* b_ao   = (const float*)d_in[7];
    const float* a_ao   = (const float*)d_in[8];
    const float* ln2    = (const float*)d_in[9];
    const float* w_fc   = (const float*)d_in[10];
    const float* b_fc   = (const float*)d_in[11];
    const float* a_fc   = (const float*)d_in[12];
    const float* w_gate = (const float*)d_in[13];
    const float* b_gate = (const float*)d_in[14];
    const float* a_gate = (const float*)d_in[15];
    const float* w_proj = (const float*)d_in[16];
    const float* b_proj = (const float*)d_in[17];
    const float* a_proj = (const float*)d_in[18];
    float* out = (float*)d_out;

    float *h, *qkv, *o, *x1, *h2, *gate, *u, *rn, *cn;
    cudaGetSymbolAddress((void**)&h,    g_h);
    cudaGetSymbolAddress((void**)&qkv,  g_qkv);
    cudaGetSymbolAddress((void**)&o,    g_o);
    cudaGetSymbolAddress((void**)&x1,   g_x1);
    cudaGetSymbolAddress((void**)&h2,   g_h2);
    cudaGetSymbolAddress((void**)&gate, g_gate);
    cudaGetSymbolAddress((void**)&u,    g_u);
    cudaGetSymbolAddress((void**)&rn,   g_rn);
    cudaGetSymbolAddress((void**)&cn,   g_cn);

    // 1. LN1 + ||h||^2
    ln_kernel<<<Mrows, 256>>>(x, ln1, h, rn);

    // 2. qkv = yat(h @ w_qkv)
    colnorm_kernel<<<(3*Cc+255)/256, 256>>>(w_qkv, cn, Cc, 3*Cc);
    gemm_yat<0><<<dim3(3*Cc/BN, Mrows/BM), 256>>>(h, w_qkv, qkv, rn, cn,
                                                  b_qkv, a_qkv, nullptr,
                                                  Mrows, 3*Cc, Cc);
    // 3. rope on q,k
    rope_kernel<<<(Mrows*Cc+255)/256, 256>>>(qkv);

    // 4. attention
    flash_attn<<<dim3(Tt/64, Hh, Bb), 256>>>(qkv, o);

    // 5. x1 = x + yat(o @ w_ao)
    rownorm_kernel<<<Mrows, 256>>>(o, rn, Cc);
    colnorm_kernel<<<(Cc+255)/256, 256>>>(w_ao, cn, Cc, Cc);
    gemm_yat<1><<<dim3(Cc/BN, Mrows/BM), 256>>>(o, w_ao, x1, rn, cn,
                                                b_ao, a_ao, x,
                                                Mrows, Cc, Cc);
    // 6. LN2 + ||h2||^2
    ln_kernel<<<Mrows, 256>>>(x1, ln2, h2, rn);

    // 7. gate = yat(h2 @ w_fc)
    colnorm_kernel<<<(HID+255)/256, 256>>>(w_fc, cn, Cc, HID);
    gemm_yat<0><<<dim3(HID/BN, Mrows/BM), 256>>>(h2, w_fc, gate, rn, cn,
                                                 b_fc, a_fc, nullptr,
                                                 Mrows, HID, Cc);
    // 8. u = gelu(yat(h2 @ w_gate)) * gate
    colnorm_kernel<<<(HID+255)/256, 256>>>(w_gate, cn, Cc, HID);
    gemm_yat<2><<<dim3(HID/BN, Mrows/BM), 256>>>(h2, w_gate, u, rn, cn,
                                                 b_gate, a_gate, gate,
                                                 Mrows, HID, Cc);
    // 9. out = x1 + yat(u @ w_proj)
    rownorm_kernel<<<Mrows, 256>>>(u, rn, HID);
    colnorm_kernel<<<(Cc+255)/256, 256>>>(w_proj, cn, HID, Cc);
    gemm_yat<1><<<dim3(Cc/BN, Mrows/BM), 256>>>(u, w_proj, out, rn, cn,
                                                b_proj, a_proj, x1,
                                                Mrows, Cc, HID);
}

// round 5
// speedup vs baseline: 1.7777x; 1.7777x over previous
#include <cstdint>
#include <cstddef>
#include <cuda_runtime.h>
#include <cuda_bf16.h>
#include <math.h>
#include <float.h>

#define Bb   2
#define Tt   1024
#define Cc   768
#define Hh   12
#define HID  3072
#define Mrows (Bb*Tt)          // 2048

// ---------------- scratch (static device arrays; no cudaMalloc) ----------------
__device__ float g_qkv [Mrows*3*Cc];            // fp32 (attention consumes)
__device__ float g_x1  [Mrows*Cc];              // fp32 residual
__device__ float g_rn  [Mrows];
__device__ float g_cn  [HID];
__device__ __nv_bfloat16 g_h   [Mrows*Cc];      // LN1 out (GEMM A)
__device__ __nv_bfloat16 g_o   [Mrows*Cc];      // attn out (GEMM A)
__device__ __nv_bfloat16 g_h2  [Mrows*Cc];      // LN2 out (GEMM A)
__device__ __nv_bfloat16 g_gate[Mrows*HID];     // fc out
__device__ __nv_bfloat16 g_u   [Mrows*HID];     // gelu*gate out (GEMM A)
__device__ __nv_bfloat16 g_wq  [Cc*3*Cc];
__device__ __nv_bfloat16 g_wao [Cc*Cc];
__device__ __nv_bfloat16 g_wfc [Cc*HID];
__device__ __nv_bfloat16 g_wg  [Cc*HID];
__device__ __nv_bfloat16 g_wp  [HID*Cc];

// ---------------- helpers ------------------------------------------------------
__device__ __forceinline__ float blockReduceSum(float v) {
    __shared__ float sh[8];
    int lane = threadIdx.x & 31, w = threadIdx.x >> 5;
    #pragma unroll
    for (int o = 16; o; o >>= 1) v += __shfl_xor_sync(0xffffffffu, v, o);
    __syncthreads();
    if (lane == 0) sh[w] = v;
    __syncthreads();
    return sh[0]+sh[1]+sh[2]+sh[3]+sh[4]+sh[5]+sh[6]+sh[7];
}

__device__ __forceinline__ float gelu_tanh(float x) {
    float x3 = x * x * x;
    float t  = tanhf(0.7978845608028654f * (x + 0.044715f * x3));
    return 0.5f * x * (1.0f + t);
}

__device__ __forceinline__ float to_f32(float v)          { return v; }
__device__ __forceinline__ float to_f32(__nv_bfloat16 v)  { return __bfloat162float(v); }

// ---------------- PTX wrappers --------------------------------------------------
__device__ __forceinline__ void cp_async16(uint32_t smem, const void* gmem) {
    asm volatile("cp.async.cg.shared.global [%0],[%1],16;\n" :: "r"(smem), "l"(gmem));
}
__device__ __forceinline__ void cp_commit() {
    asm volatile("cp.async.commit_group;\n" ::: "memory");
}
__device__ __forceinline__ void cp_wait0() {
    asm volatile("cp.async.wait_group 0;\n" ::: "memory");
}
__device__ __forceinline__ void ldsm_x4(uint32_t& r0, uint32_t& r1, uint32_t& r2, uint32_t& r3,
                                        uint32_t addr) {
    asm volatile("ldmatrix.sync.aligned.m8n8.x4.shared.b16 {%0,%1,%2,%3},[%4];\n"
                 : "=r"(r0), "=r"(r1), "=r"(r2), "=r"(r3) : "r"(addr));
}
__device__ __forceinline__ void ldsm_x4_t(uint32_t& r0, uint32_t& r1, uint32_t& r2, uint32_t& r3,
                                          uint32_t addr) {
    asm volatile("ldmatrix.sync.aligned.m8n8.x4.trans.shared.b16 {%0,%1,%2,%3},[%4];\n"
                 : "=r"(r0), "=r"(r1), "=r"(r2), "=r"(r3) : "r"(addr));
}
__device__ __forceinline__ void mma16816(float* d, const uint32_t* a, uint32_t b0, uint32_t b1) {
    asm volatile("mma.sync.aligned.m16n8k16.row.col.f32.bf16.bf16.f32 "
                 "{%0,%1,%2,%3},{%4,%5,%6,%7},{%8,%9},{%0,%1,%2,%3};\n"
                 : "+f"(d[0]), "+f"(d[1]), "+f"(d[2]), "+f"(d[3])
                 : "r"(a[0]), "r"(a[1]), "r"(a[2]), "r"(a[3]), "r"(b0), "r"(b1));
}

// ---------------- fp32 -> bf16 convert ------------------------------------------
__global__ __launch_bounds__(256)
void f2bf(const float* __restrict__ in, __nv_bfloat16* __restrict__ out, int n)
{
    int i = (blockIdx.x * 256 + threadIdx.x) * 4;
    if (i < n) {
        float4 v = *(const float4*)(in + i);
        *(__nv_bfloat162*)(out + i)     = __floats2bfloat162_rn(v.x, v.y);
        *(__nv_bfloat162*)(out + i + 2) = __floats2bfloat162_rn(v.z, v.w);
    }
}

// ---------------- LayerNorm -> bf16 h, fp32 rownorm -----------------------------
__global__ __launch_bounds__(256)
void ln_kernel(const float* __restrict__ x, const float* __restrict__ sc,
               __nv_bfloat16* __restrict__ h, float* __restrict__ rn)
{
    int row = blockIdx.x;
    const float* xr = x + (size_t)row * Cc;
    int t = threadIdx.x;
    float v0 = xr[t], v1 = xr[t+256], v2 = xr[t+512];
    float s  = blockReduceSum(v0+v1+v2);
    float ss = blockReduceSum(v0*v0+v1*v1+v2*v2);
    float mu  = s  * (1.0f/768.0f);
    float var = ss * (1.0f/768.0f) - mu*mu;
    float rs  = rsqrtf(var + 1e-6f);
    float o0 = (v0-mu)*rs*sc[t];
    float o1 = (v1-mu)*rs*sc[t+256];
    float o2 = (v2-mu)*rs*sc[t+512];
    __nv_bfloat16* hr = h + (size_t)row * Cc;
    hr[t] = __float2bfloat16(o0);
    hr[t+256] = __float2bfloat16(o1);
    hr[t+512] = __float2bfloat16(o2);
    float hn = blockReduceSum(o0*o0+o1*o1+o2*o2);
    if (t == 0) rn[row] = hn;
}

// ---------------- rownorm over bf16 ---------------------------------------------
__global__ __launch_bounds__(256)
void rownorm_bf16(const __nv_bfloat16* __restrict__ a, float* __restrict__ rn, int C)
{
    int row = blockIdx.x;
    const __nv_bfloat16* ar = a + (size_t)row * C;
    float s = 0.f;
    for (int c = threadIdx.x; c < C; c += 256) {
        float v = __bfloat162float(ar[c]); s += v*v;
    }
    s = blockReduceSum(s);
    if (threadIdx.x == 0) rn[row] = s;
}

// ---------------- column norms of fp32 W (K x N row-major) ----------------------
__global__ __launch_bounds__(256)
void colnorm_kernel(const float* __restrict__ W, float* __restrict__ cn, int K, int N)
{
    int n = blockIdx.x * 256 + threadIdx.x;
    if (n >= N) return;
    float s = 0.f;
    for (int k = 0; k < K; k++) { float v = W[(size_t)k * N + n]; s += v*v; }
    cn[n] = s;
}

// ---------------- elementwise "rope" on fp32 qkv --------------------------------
__global__ __launch_bounds__(256)
void rope_kernel(float* __restrict__ qkv)
{
    int i = blockIdx.x * 256 + threadIdx.x;
    if (i >= Mrows * Cc) return;
    int hd  = i % Cc;
    int row = i / Cc;
    int t   = row % Tt;
    int d   = hd & 63;
    int ii  = d & 31;
    float freq = expf((float)(2*ii) * (-logf(10000.0f) / 64.0f));
    float ang  = (float)t * freq;
    float r    = (d < 32) ? cosf(ang) : sinf(ang);
    size_t base = (size_t)row * (3*Cc);
    qkv[base + hd]      *= r;
    qkv[base + Cc + hd] *= r;
}

// ---------------- bf16 tensor-core GEMM + yat epilogue --------------------------
// out[m,n] = epi( sum_k A[m,k]*W[k,n] )
// MODE 0: yat    MODE 1: extra + yat    MODE 2: gelu(yat)*extra
#define GLDA 40    // As row stride (bf16 elems), conflict-free padding
#define GLDB 136   // Bs row stride

template<int MODE, typename OutT, typename ExtraT>
__global__ __launch_bounds__(256)
void gemm_yat_mma(const __nv_bfloat16* __restrict__ A, const __nv_bfloat16* __restrict__ W,
                  OutT* __restrict__ out,
                  const float* __restrict__ rn, const float* __restrict__ cn,
                  const float* __restrict__ bias, const float* __restrict__ alphap,
                  const ExtraT* __restrict__ extra,
                  int M, int N, int K)
{
    __shared__ __nv_bfloat16 As[2][128*GLDA];
    __shared__ __nv_bfloat16 Bs[2][32*GLDB];
    const int tid = threadIdx.x;
    const int m0 = blockIdx.y * 128, n0 = blockIdx.x * 128;

    // cp.async mapping: A tile 128x32, B tile 32x128; 32B per thread per tile
    const int a_row = tid >> 1, a_col = (tid & 1) * 16;
    const int b_row = tid >> 3, b_col = (tid & 7) * 16;
    const char* Ag = (const char*)(A + (size_t)(m0 + a_row) * K + a_col);
    const char* Bg = (const char*)(W + (size_t)b_row * N + n0 + b_col);
    const uint32_t As0 = (uint32_t)__cvta_generic_to_shared(&As[0][0]);
    const uint32_t Bs0 = (uint32_t)__cvta_generic_to_shared(&Bs[0][0]);
    const uint32_t Asw = As0 + (uint32_t)(a_row*GLDA + a_col)*2u;
    const uint32_t Bsw = Bs0 + (uint32_t)(b_row*GLDB + b_col)*2u;
    const uint32_t AS_STG = 128u*GLDA*2u, BS_STG = 32u*GLDB*2u;

    const int lane = tid & 31, warp = tid >> 5;
    const int wm = (warp >> 2) * 64;   // 0 / 64
    const int wn = (warp & 3) * 32;    // 0..96

    float acc[4][4][4];
    #pragma unroll
    for (int i = 0; i < 4; i++)
        #pragma unroll
        for (int j = 0; j < 4; j++)
            #pragma unroll
            for (int e = 0; e < 4; e++) acc[i][j][e] = 0.f;

    // ldmatrix per-lane base addresses (bytes)
    const uint32_t a_mat = As0 + (uint32_t)(((wm + (lane & 15)) * GLDA) + (lane >> 4) * 8)*2u;
    const uint32_t b_mat = Bs0 + (uint32_t)(((lane & 15) * GLDB) + wn + (lane >> 4) * 8)*2u;

    const int KT = K >> 5;
    // prefetch tile 0 -> stage 0
    cp_async16(Asw, Ag);        cp_async16(Asw + 16u, Ag + 16);
    cp_async16(Bsw, Bg);        cp_async16(Bsw + 16u, Bg + 16);
    cp_commit();

    for (int kt = 0; kt < KT; kt++) {
        cp_wait0();
        __syncthreads();
        if (kt + 1 < KT) {
            uint32_t stg = (uint32_t)((kt + 1) & 1);
            const char* ag = Ag + (size_t)(kt + 1) * 64;          // 32 bf16 per K step
            const char* bg = Bg + (size_t)(kt + 1) * 32 * N * 2;
            uint32_t asd = Asw + stg * AS_STG;
            uint32_t bsd = Bsw + stg * BS_STG;
            cp_async16(asd, ag);        cp_async16(asd + 16u, ag + 16);
            cp_async16(bsd, bg);        cp_async16(bsd + 16u, bg + 16);
            cp_commit();
        }
        uint32_t cur = (uint32_t)(kt & 1);
        uint32_t abase = a_mat + cur * AS_STG;
        uint32_t bbase = b_mat + cur * BS_STG;
        #pragma unroll
        for (int kk = 0; kk < 2; kk++) {
            uint32_t ra[4][4];
            uint32_t rb[2][4];
            #pragma unroll
            for (int mt = 0; mt < 4; mt++)
                ldsm_x4(ra[mt][0], ra[mt][1], ra[mt][2], ra[mt][3],
                        abase + (uint32_t)(mt*16*GLDA + kk*16)*2u);
            #pragma unroll
            for (int p = 0; p < 2; p++)
                ldsm_x4_t(rb[p][0], rb[p][1], rb[p][2], rb[p][3],
                          bbase + (uint32_t)(kk*16*GLDB + p*16)*2u);
            #pragma unroll
            for (int mt = 0; mt < 4; mt++)
                #pragma unroll
                for (int nt = 0; nt < 4; nt++)
                    mma16816(acc[mt][nt], ra[mt],
                             rb[nt>>1][(nt&1)*2], rb[nt>>1][(nt&1)*2 + 1]);
        }
    }

    // --- yat epilogue (fp32) ---
    float sc = powf(sqrtf((float)N) / log1pf((float)N), alphap[0]);
    #pragma unroll
    for (int mt = 0; mt < 4; mt++) {
        #pragma unroll
        for (int half = 0; half < 2; half++) {
            int m = m0 + wm + mt*16 + (lane >> 2) + half*8;
            float rnv = rn[m];
            #pragma unroll
            for (int nt = 0; nt < 4; nt++) {
                int n = n0 + wn + nt*8 + (lane & 3)*2;
                float y0 = acc[mt][nt][half*2 + 0];
                float y1 = acc[mt][nt][half*2 + 1];
                float d0 = rnv + cn[n]   - 2.0f*y0 + 1e-6f;
                float d1 = rnv + cn[n+1] - 2.0f*y1 + 1e-6f;
                float v0 = (y0*y0/d0 + bias[n])   * sc;
                float v1 = (y1*y1/d1 + bias[n+1]) * sc;
                if constexpr (MODE == 1) {
                    const ExtraT* ep = extra + (size_t)m*N + n;
                    v0 += to_f32(ep[0]); v1 += to_f32(ep[1]);
                }
                if constexpr (MODE == 2) {
                    const ExtraT* ep = extra + (size_t)m*N + n;
                    v0 = gelu_tanh(v0) * to_f32(ep[0]);
                    v1 = gelu_tanh(v1) * to_f32(ep[1]);
                }
                OutT* op = out + (size_t)m*N + n;
                if constexpr (sizeof(OutT) == 2) {
                    *(__nv_bfloat162*)op = __floats2bfloat162_rn(v0, v1);
                } else {
                    *(float2*)op = make_float2(v0, v1);
                }
            }
        }
    }
}

// ---------------- fp32 flash attention (causal, 64x64, D=64) -> bf16 o ----------
__global__ __launch_bounds__(256)
void flash_attn(const float* __restrict__ qkv, __nv_bfloat16* __restrict__ o)
{
    __shared__ float Qs[64*64];   // [d][row]
    __shared__ float KPs[64*64];  // K: [d][col] then P: [j][row]
    __shared__ float Vs[64*64];   // [j][d]

    int tid = threadIdx.x;
    int qt = blockIdx.x, h = blockIdx.y, b = blockIdx.z;
    int t0 = qt * 64;
    int ty = tid >> 4, tx = tid & 15;

    {
        int r = tid >> 2, dc = (tid & 3) * 16;
        const float* qp = qkv + ((size_t)(b*Tt + t0 + r) * (3*Cc)) + h*64 + dc;
        #pragma unroll
        for (int j = 0; j < 4; j++) {
            float4 v = *(const float4*)(qp + j*4);
            int d = dc + j*4;
            Qs[(d+0)*64 + r] = v.x; Qs[(d+1)*64 + r] = v.y;
            Qs[(d+2)*64 + r] = v.z; Qs[(d+3)*64 + r] = v.w;
        }
    }

    float mrun[4], lrun[4], acc[4][4];
    #pragma unroll
    for (int a = 0; a < 4; a++) {
        mrun[a] = -1e30f; lrun[a] = 0.f;
        #pragma unroll
        for (int c = 0; c < 4; c++) acc[a][c] = 0.f;
    }

    int nTiles = qt + 1;
    for (int jt = 0; jt < nTiles; jt++) {
        int j0 = jt * 64;
        __syncthreads();
        {
            int r = tid >> 2, dc = (tid & 3) * 16;
            const float* kp = qkv + ((size_t)(b*Tt + j0 + r) * (3*Cc)) + Cc + h*64 + dc;
            const float* vp = kp + Cc;
            #pragma unroll
            for (int j = 0; j < 4; j++) {
                float4 v = *(const float4*)(kp + j*4);
                int d = dc + j*4;
                KPs[(d+0)*64 + r] = v.x; KPs[(d+1)*64 + r] = v.y;
                KPs[(d+2)*64 + r] = v.z; KPs[(d+3)*64 + r] = v.w;
            }
            #pragma unroll
            for (int j = 0; j < 4; j++)
                *(float4*)&Vs[r*64 + dc + j*4] = *(const float4*)(vp + j*4);
        }
        __syncthreads();

        float s[4][4];
        #pragma unroll
        for (int a = 0; a < 4; a++)
            #pragma unroll
            for (int c = 0; c < 4; c++) s[a][c] = 0.f;
        #pragma unroll 8
        for (int d = 0; d < 64; d++) {
            float4 qf = *(float4*)&Qs[d*64 + ty*4];
            float4 kf = *(float4*)&KPs[d*64 + tx*4];
            float qv[4] = {qf.x,qf.y,qf.z,qf.w};
            float kv[4] = {kf.x,kf.y,kf.z,kf.w};
            #pragma unroll
            for (int a = 0; a < 4; a++)
                #pragma unroll
                for (int c = 0; c < 4; c++)
                    s[a][c] = fmaf(qv[a], kv[c], s[a][c]);
        }

        float p[4][4];
        #pragma unroll
        for (int a = 0; a < 4; a++) {
            int row = t0 + ty*4 + a;
            float mx = -1e30f;
            #pragma unroll
            for (int c = 0; c < 4; c++) {
                float sv = s[a][c] * 0.125f;
                int col = j0 + tx*4 + c;
                if (col > row) sv = -3.4028235e38f;
                s[a][c] = sv;
                mx = fmaxf(mx, sv);
            }
            #pragma unroll
            for (int off = 8; off; off >>= 1)
                mx = fmaxf(mx, __shfl_xor_sync(0xffffffffu, mx, off));
            float mn = fmaxf(mrun[a], mx);
            float corr = expf(mrun[a] - mn);
            mrun[a] = mn;
            float ls = 0.f;
            #pragma unroll
            for (int c = 0; c < 4; c++) {
                float pv = expf(s[a][c] - mn);
                p[a][c] = pv; ls += pv;
            }
            #pragma unroll
            for (int off = 8; off; off >>= 1)
                ls += __shfl_xor_sync(0xffffffffu, ls, off);
            lrun[a] = lrun[a] * corr + ls;
            #pragma unroll
            for (int c = 0; c < 4; c++) acc[a][c] *= corr;
        }

        __syncthreads();
        #pragma unroll
        for (int a = 0; a < 4; a++)
            #pragma unroll
            for (int c = 0; c < 4; c++)
                KPs[(tx*4 + c)*64 + ty*4 + a] = p[a][c];
        __syncthreads();

        #pragma unroll 8
        for (int j = 0; j < 64; j++) {
            float4 pf = *(float4*)&KPs[j*64 + ty*4];
            float4 vf = *(float4*)&Vs[j*64 + tx*4];
            float pv[4] = {pf.x,pf.y,pf.z,pf.w};
            float vv[4] = {vf.x,vf.y,vf.z,vf.w};
            #pragma unroll
            for (int a = 0; a < 4; a++)
                #pragma unroll
                for (int c = 0; c < 4; c++)
                    acc[a][c] = fmaf(pv[a], vv[c], acc[a][c]);
        }
    }

    #pragma unroll
    for (int a = 0; a < 4; a++) {
        int row = t0 + ty*4 + a;
        float inv = 1.0f / lrun[a];
        __nv_bfloat16* op = o + (size_t)(b*Tt + row)*Cc + h*64 + tx*4;
        *(__nv_bfloat162*)op       = __floats2bfloat162_rn(acc[a][0]*inv, acc[a][1]*inv);
        *(__nv_bfloat162*)(op + 2) = __floats2bfloat162_rn(acc[a][2]*inv, acc[a][3]*inv);
    }
}

// ---------------- launch --------------------------------------------------------
extern "C" void kernel_launch(void* const* d_in, const int* in_sizes, int n_in,
                              void* d_out, int out_size)
{
    (void)in_sizes; (void)n_in; (void)out_size;
    const float* x      = (const float*)d_in[0];
    const float* ln1    = (const float*)d_in[2];
    const float* w_qkv  = (const float*)d_in[3];
    const float* b_qkv  = (const float*)d_in[4];
    const float* a_qkv  = (const float*)d_in[5];
    const float* w_ao   = (const float*)d_in[6];
    const float* b_ao   = (const float*)d_in[7];
    const float* a_ao   = (const float*)d_in[8];
    const float* ln2    = (const float*)d_in[9];
    const float* w_fc   = (const float*)d_in[10];
    const float* b_fc   = (const float*)d_in[11];
    const float* a_fc   = (const float*)d_in[12];
    const float* w_gate = (const float*)d_in[13];
    const float* b_gate = (const float*)d_in[14];
    const float* a_gate = (const float*)d_in[15];
    const float* w_proj = (const float*)d_in[16];
    const float* b_proj = (const float*)d_in[17];
    const float* a_proj = (const float*)d_in[18];
    float* out = (float*)d_out;

    float *qkv, *x1, *rn, *cn;
    __nv_bfloat16 *h, *o, *h2, *gate, *u, *wq, *wao, *wfc, *wg, *wp;
    cudaGetSymbolAddress((void**)&qkv,  g_qkv);
    cudaGetSymbolAddress((void**)&x1,   g_x1);
    cudaGetSymbolAddress((void**)&rn,   g_rn);
    cudaGetSymbolAddress((void**)&cn,   g_cn);
    cudaGetSymbolAddress((void**)&h,    g_h);
    cudaGetSymbolAddress((void**)&o,    g_o);
    cudaGetSymbolAddress((void**)&h2,   g_h2);
    cudaGetSymbolAddress((void**)&gate, g_gate);
    cudaGetSymbolAddress((void**)&u,    g_u);
    cudaGetSymbolAddress((void**)&wq,   g_wq);
    cudaGetSymbolAddress((void**)&wao,  g_wao);
    cudaGetSymbolAddress((void**)&wfc,  g_wfc);
    cudaGetSymbolAddress((void**)&wg,   g_wg);
    cudaGetSymbolAddress((void**)&wp,   g_wp);

    // weight bf16 conversions
    f2bf<<<(Cc*3*Cc/4 + 255)/256, 256>>>(w_qkv,  wq,  Cc*3*Cc);
    f2bf<<<(Cc*Cc/4   + 255)/256, 256>>>(w_ao,   wao, Cc*Cc);
    f2bf<<<(Cc*HID/4  + 255)/256, 256>>>(w_fc,   wfc, Cc*HID);
    f2bf<<<(Cc*HID/4  + 255)/256, 256>>>(w_gate, wg,  Cc*HID);
    f2bf<<<(HID*Cc/4  + 255)/256, 256>>>(w_proj, wp,  HID*Cc);

    // 1. LN1 -> h (bf16), rn
    ln_kernel<<<Mrows, 256>>>(x, ln1, h, rn);

    // 2. qkv = yat(h @ w_qkv)  (fp32 out)
    colnorm_kernel<<<(3*Cc+255)/256, 256>>>(w_qkv, cn, Cc, 3*Cc);
    gemm_yat_mma<0, float, float><<<dim3(3*Cc/128, Mrows/128), 256>>>(
        h, wq, qkv, rn, cn, b_qkv, a_qkv, (const float*)nullptr, Mrows, 3*Cc, Cc);

    // 3. rope
    rope_kernel<<<(Mrows*Cc+255)/256, 256>>>(qkv);

    // 4. attention -> o (bf16)
    flash_attn<<<dim3(Tt/64, Hh, Bb), 256>>>(qkv, o);

    // 5. x1 = x + yat(o @ w_ao)  (fp32 out)
    rownorm_bf16<<<Mrows, 256>>>(o, rn, Cc);
    colnorm_kernel<<<(Cc+255)/256, 256>>>(w_ao, cn, Cc, Cc);
    gemm_yat_mma<1, float, float><<<dim3(Cc/128, Mrows/128), 256>>>(
        o, wao, x1, rn, cn, b_ao, a_ao, x, Mrows, Cc, Cc);

    // 6. LN2 -> h2 (bf16), rn
    ln_kernel<<<Mrows, 256>>>(x1, ln2, h2, rn);

    // 7. gate = yat(h2 @ w_fc)  (bf16 out)
    colnorm_kernel<<<(HID+255)/256, 256>>>(w_fc, cn, Cc, HID);
    gemm_yat_mma<0, __nv_bfloat16, float><<<dim3(HID/128, Mrows/128), 256>>>(
        h2, wfc, gate, rn, cn, b_fc, a_fc, (const float*)nullptr, Mrows, HID, Cc);

    // 8. u = gelu(yat(h2 @ w_gate)) * gate  (bf16 out)
    colnorm_kernel<<<(HID+255)/256, 256>>>(w_gate, cn, Cc, HID);
    gemm_yat_mma<2, __nv_bfloat16, __nv_bfloat16><<<dim3(HID/128, Mrows/128), 256>>>(
        h2, wg, u, rn, cn, b_gate, a_gate, gate, Mrows, HID, Cc);

    // 9. out = x1 + yat(u @ w_proj)  (fp32 out)
    rownorm_bf16<<<Mrows, 256>>>(u, rn, HID);
    colnorm_kernel<<<(Cc+255)/256, 256>>>(w_proj, cn, HID, Cc);
    gemm_yat_mma<1, float, float><<<dim3(Cc/128, Mrows/128), 256>>>(
        u, wp, out, rn, cn, b_proj, a_proj, x1, Mrows, Cc, HID);
}

// round 6
// speedup vs baseline: 4.2873x; 2.4118x over previous
#include <cstdint>
#include <cstddef>
#include <cuda_runtime.h>
#include <cuda_bf16.h>
#include <math.h>

#define Bb   2
#define Tt   1024
#define Cc   768
#define Hh   12
#define HID  3072
#define Mrows (Bb*Tt)          // 2048

// ---------------- scratch (static device arrays; no cudaMalloc) ----------------
__device__ float g_x1  [Mrows*Cc];              // fp32 residual
__device__ float g_rn  [Mrows];
__device__ float g_cn  [HID];
__device__ float g_part[36864];                 // split-K colnorm partials
__device__ float g_rope[Tt*64];                 // rope table
__device__ __nv_bfloat16 g_qkvb[Mrows*3*Cc];    // bf16 qkv (rope+scale applied)
__device__ __nv_bfloat16 g_h   [Mrows*Cc];
__device__ __nv_bfloat16 g_o   [Mrows*Cc];
__device__ __nv_bfloat16 g_h2  [Mrows*Cc];
__device__ __nv_bfloat16 g_gate[Mrows*HID];
__device__ __nv_bfloat16 g_u   [Mrows*HID];
__device__ __nv_bfloat16 g_wq  [Cc*3*Cc];
__device__ __nv_bfloat16 g_wao [Cc*Cc];
__device__ __nv_bfloat16 g_wfc [Cc*HID];
__device__ __nv_bfloat16 g_wg  [Cc*HID];
__device__ __nv_bfloat16 g_wp  [HID*Cc];

// ---------------- helpers ------------------------------------------------------
__device__ __forceinline__ float blockReduceSum(float v) {
    __shared__ float sh[8];
    int lane = threadIdx.x & 31, w = threadIdx.x >> 5;
    #pragma unroll
    for (int o = 16; o; o >>= 1) v += __shfl_xor_sync(0xffffffffu, v, o);
    __syncthreads();
    if (lane == 0) sh[w] = v;
    __syncthreads();
    return sh[0]+sh[1]+sh[2]+sh[3]+sh[4]+sh[5]+sh[6]+sh[7];
}

__device__ __forceinline__ float gelu_tanh(float x) {
    float x3 = x * x * x;
    float t  = tanhf(0.7978845608028654f * (x + 0.044715f * x3));
    return 0.5f * x * (1.0f + t);
}

__device__ __forceinline__ float to_f32(float v)          { return v; }
__device__ __forceinline__ float to_f32(__nv_bfloat16 v)  { return __bfloat162float(v); }

__device__ __forceinline__ uint32_t pack2(float a, float b) {
    __nv_bfloat162 t = __floats2bfloat162_rn(a, b);
    return *(uint32_t*)&t;
}

// ---------------- PTX wrappers --------------------------------------------------
__device__ __forceinline__ void cp_async16(uint32_t smem, const void* gmem) {
    asm volatile("cp.async.cg.shared.global [%0],[%1],16;\n" :: "r"(smem), "l"(gmem));
}
__device__ __forceinline__ void cp_commit() {
    asm volatile("cp.async.commit_group;\n" ::: "memory");
}
__device__ __forceinline__ void cp_wait0() {
    asm volatile("cp.async.wait_group 0;\n" ::: "memory");
}
__device__ __forceinline__ void cp_wait1() {
    asm volatile("cp.async.wait_group 1;\n" ::: "memory");
}
__device__ __forceinline__ void cp_wait2() {
    asm volatile("cp.async.wait_group 2;\n" ::: "memory");
}
__device__ __forceinline__ void ldsm_x4(uint32_t& r0, uint32_t& r1, uint32_t& r2, uint32_t& r3,
                                        uint32_t addr) {
    asm volatile("ldmatrix.sync.aligned.m8n8.x4.shared.b16 {%0,%1,%2,%3},[%4];\n"
                 : "=r"(r0), "=r"(r1), "=r"(r2), "=r"(r3) : "r"(addr));
}
__device__ __forceinline__ void ldsm_x4_t(uint32_t& r0, uint32_t& r1, uint32_t& r2, uint32_t& r3,
                                          uint32_t addr) {
    asm volatile("ldmatrix.sync.aligned.m8n8.x4.trans.shared.b16 {%0,%1,%2,%3},[%4];\n"
                 : "=r"(r0), "=r"(r1), "=r"(r2), "=r"(r3) : "r"(addr));
}
__device__ __forceinline__ void mma16816(float* d, const uint32_t* a, uint32_t b0, uint32_t b1) {
    asm volatile("mma.sync.aligned.m16n8k16.row.col.f32.bf16.bf16.f32 "
                 "{%0,%1,%2,%3},{%4,%5,%6,%7},{%8,%9},{%0,%1,%2,%3};\n"
                 : "+f"(d[0]), "+f"(d[1]), "+f"(d[2]), "+f"(d[3])
                 : "r"(a[0]), "r"(a[1]), "r"(a[2]), "r"(a[3]), "r"(b0), "r"(b1));
}

// ---------------- rope table ----------------------------------------------------
__global__ __launch_bounds__(256)
void rope_tab(float* __restrict__ tab)
{
    int i = blockIdx.x * 256 + threadIdx.x;     // Tt*64 = 65536
    int t = i >> 6, d = i & 63, ii = d & 31;
    float fr  = expf(-(float)(2*ii) * (logf(10000.0f) / 64.0f));
    float ang = (float)t * fr;
    tab[i] = (d < 32) ? cosf(ang) : sinf(ang);
}

// ---------------- fused weight convert + split-K column-norm partials -----------
// grid (N/256, K/64): block converts a 64xK-chunk x 256-col tile, writes partial sums
__global__ __launch_bounds__(256)
void wconv(const float* __restrict__ W, __nv_bfloat16* __restrict__ Wb,
           float* __restrict__ part, int N)
{
    int n  = blockIdx.x * 256 + threadIdx.x;
    int k0 = blockIdx.y * 64;
    float s = 0.f;
    #pragma unroll 4
    for (int k = k0; k < k0 + 64; k++) {
        float v = W[(size_t)k * N + n];
        Wb[(size_t)k * N + n] = __float2bfloat16(v);
        s += v * v;
    }
    part[(size_t)blockIdx.y * N + n] = s;
}

__global__ __launch_bounds__(256)
void colreduce(const float* __restrict__ part, float* __restrict__ cn, int N, int nch)
{
    int n = blockIdx.x * 256 + threadIdx.x;
    if (n >= N) return;
    float s = 0.f;
    for (int c = 0; c < nch; c++) s += part[(size_t)c * N + n];
    cn[n] = s;
}

// ---------------- LayerNorm -> bf16 h, fp32 rownorm -----------------------------
__global__ __launch_bounds__(256)
void ln_kernel(const float* __restrict__ x, const float* __restrict__ sc,
               __nv_bfloat16* __restrict__ h, float* __restrict__ rn)
{
    int row = blockIdx.x;
    const float* xr = x + (size_t)row * Cc;
    int t = threadIdx.x;
    float v0 = xr[t], v1 = xr[t+256], v2 = xr[t+512];
    float s  = blockReduceSum(v0+v1+v2);
    float ss = blockReduceSum(v0*v0+v1*v1+v2*v2);
    float mu  = s  * (1.0f/768.0f);
    float var = ss * (1.0f/768.0f) - mu*mu;
    float rs  = rsqrtf(var + 1e-6f);
    float o0 = (v0-mu)*rs*sc[t];
    float o1 = (v1-mu)*rs*sc[t+256];
    float o2 = (v2-mu)*rs*sc[t+512];
    __nv_bfloat16* hr = h + (size_t)row * Cc;
    hr[t] = __float2bfloat16(o0);
    hr[t+256] = __float2bfloat16(o1);
    hr[t+512] = __float2bfloat16(o2);
    float hn = blockReduceSum(o0*o0+o1*o1+o2*o2);
    if (t == 0) rn[row] = hn;
}

// ---------------- rownorm over bf16 ---------------------------------------------
__global__ __launch_bounds__(256)
void rownorm_bf16(const __nv_bfloat16* __restrict__ a, float* __restrict__ rn, int C)
{
    int row = blockIdx.x;
    const __nv_bfloat16* ar = a + (size_t)row * C;
    float s = 0.f;
    for (int c = threadIdx.x; c < C; c += 256) {
        float v = __bfloat162float(ar[c]); s += v*v;
    }
    s = blockReduceSum(s);
    if (threadIdx.x == 0) rn[row] = s;
}

// ---------------- bf16 tensor-core GEMM + yat epilogue --------------------------
// MODE 0: yat   MODE 1: extra + yat   MODE 2: gelu(yat)*extra
// MODE 3: qkv — rope table in `extra`, q gets extra 1/8 scale; bf16 out
#define GLDA 40
#define GLDB 136
#define GSTAGES 4

template<int MODE, typename OutT, typename ExtraT>
__global__ __launch_bounds__(256)
void gemm_yat_mma(const __nv_bfloat16* __restrict__ A, const __nv_bfloat16* __restrict__ W,
                  OutT* __restrict__ out,
                  const float* __restrict__ rn, const float* __restrict__ cn,
                  const float* __restrict__ bias, const float* __restrict__ alphap,
                  const ExtraT* __restrict__ extra,
                  int M, int N, int K)
{
    extern __shared__ __nv_bfloat16 smem[];
    __nv_bfloat16* As = smem;                         // GSTAGES * 128*GLDA
    __nv_bfloat16* Bs = smem + GSTAGES*128*GLDA;      // GSTAGES * 32*GLDB
    const int tid = threadIdx.x;
    const int m0 = blockIdx.y * 128, n0 = blockIdx.x * 128;

    const int a_row = tid >> 1, a_col = (tid & 1) * 16;
    const int b_row = tid >> 3, b_col = (tid & 7) * 16;
    const char* Ag = (const char*)(A + (size_t)(m0 + a_row) * K + a_col);
    const char* Bg = (const char*)(W + (size_t)b_row * N + n0 + b_col);
    const uint32_t As0 = (uint32_t)__cvta_generic_to_shared(As);
    const uint32_t Bs0 = (uint32_t)__cvta_generic_to_shared(Bs);
    const uint32_t Asw = As0 + (uint32_t)(a_row*GLDA + a_col)*2u;
    const uint32_t Bsw = Bs0 + (uint32_t)(b_row*GLDB + b_col)*2u;
    const uint32_t AS_STG = 128u*GLDA*2u, BS_STG = 32u*GLDB*2u;

    const int lane = tid & 31, warp = tid >> 5;
    const int wm = (warp >> 2) * 64;
    const int wn = (warp & 3) * 32;

    float acc[4][4][4];
    #pragma unroll
    for (int i = 0; i < 4; i++)
        #pragma unroll
        for (int j = 0; j < 4; j++)
            #pragma unroll
            for (int e = 0; e < 4; e++) acc[i][j][e] = 0.f;

    const uint32_t a_mat = As0 + (uint32_t)(((wm + (lane & 15)) * GLDA) + (lane >> 4) * 8)*2u;
    const uint32_t b_mat = Bs0 + (uint32_t)(((lane & 15) * GLDB) + wn + (lane >> 4) * 8)*2u;

    const int KT = K >> 5;

    auto issueT = [&](int kt) {
        uint32_t stg = (uint32_t)(kt & (GSTAGES-1));
        const char* ag = Ag + (size_t)kt * 64;            // 32 bf16 per k-step
        const char* bg = Bg + (size_t)kt * 32 * N * 2;
        uint32_t asd = Asw + stg * AS_STG;
        uint32_t bsd = Bsw + stg * BS_STG;
        cp_async16(asd, ag);        cp_async16(asd + 16u, ag + 16);
        cp_async16(bsd, bg);        cp_async16(bsd + 16u, bg + 16);
        cp_commit();
    };

    issueT(0); issueT(1); issueT(2);

    for (int kt = 0; kt < KT; kt++) {
        int rem = KT - 1 - kt;                      // groups committed after kt
        if (rem >= 2)      cp_wait2();
        else if (rem == 1) cp_wait1();
        else               cp_wait0();
        __syncthreads();
        if (kt + 3 < KT) issueT(kt + 3);

        uint32_t stg = (uint32_t)(kt & (GSTAGES-1));
        uint32_t abase = a_mat + stg * AS_STG;
        uint32_t bbase = b_mat + stg * BS_STG;
        #pragma unroll
        for (int kk = 0; kk < 2; kk++) {
            uint32_t ra[4][4];
            uint32_t rb[2][4];
            #pragma unroll
            for (int mt = 0; mt < 4; mt++)
                ldsm_x4(ra[mt][0], ra[mt][1], ra[mt][2], ra[mt][3],
                        abase + (uint32_t)(mt*16*GLDA + kk*16)*2u);
            #pragma unroll
            for (int p = 0; p < 2; p++)
                ldsm_x4_t(rb[p][0], rb[p][1], rb[p][2], rb[p][3],
                          bbase + (uint32_t)(kk*16*GLDB + p*16)*2u);
            #pragma unroll
            for (int mt = 0; mt < 4; mt++)
                #pragma unroll
                for (int nt = 0; nt < 4; nt++)
                    mma16816(acc[mt][nt], ra[mt],
                             rb[nt>>1][(nt&1)*2], rb[nt>>1][(nt&1)*2 + 1]);
        }
    }

    // --- yat epilogue (fp32) ---
    float sc = powf(sqrtf((float)N) / log1pf((float)N), alphap[0]);
    #pragma unroll
    for (int mt = 0; mt < 4; mt++) {
        #pragma unroll
        for (int half = 0; half < 2; half++) {
            int m = m0 + wm + mt*16 + (lane >> 2) + half*8;
            float rnv = rn[m];
            #pragma unroll
            for (int nt = 0; nt < 4; nt++) {
                int n = n0 + wn + nt*8 + (lane & 3)*2;
                float y0 = acc[mt][nt][half*2 + 0];
                float y1 = acc[mt][nt][half*2 + 1];
                float d0 = rnv + cn[n]   - 2.0f*y0 + 1e-6f;
                float d1 = rnv + cn[n+1] - 2.0f*y1 + 1e-6f;
                float v0 = (y0*y0/d0 + bias[n])   * sc;
                float v1 = (y1*y1/d1 + bias[n+1]) * sc;
                if constexpr (MODE == 1) {
                    const ExtraT* ep = extra + (size_t)m*N + n;
                    v0 += to_f32(ep[0]); v1 += to_f32(ep[1]);
                }
                if constexpr (MODE == 2) {
                    const ExtraT* ep = extra + (size_t)m*N + n;
                    v0 = gelu_tanh(v0) * to_f32(ep[0]);
                    v1 = gelu_tanh(v1) * to_f32(ep[1]);
                }
                if constexpr (MODE == 3) {
                    if (n < 2*Cc) {
                        int t  = m % Tt;
                        int dd = n & 63;
                        float f0 = extra[t*64 + dd], f1 = extra[t*64 + dd + 1];
                        if (n < Cc) { f0 *= 0.125f; f1 *= 0.125f; }
                        v0 *= f0; v1 *= f1;
                    }
                }
                OutT* op = out + (size_t)m*N + n;
                if constexpr (sizeof(OutT) == 2) {
                    *(__nv_bfloat162*)op = __floats2bfloat162_rn(v0, v1);
                } else {
                    *(float2*)op = make_float2(v0, v1);
                }
            }
        }
    }
}

// ---------------- bf16 mma flash attention (causal, 64q x 64k, D=64) ------------
#define ALDK 72
__global__ __launch_bounds__(128)
void flash_attn_mma(const __nv_bfloat16* __restrict__ qkv, __nv_bfloat16* __restrict__ o)
{
    __shared__ __nv_bfloat16 Ks[2][64*ALDK];
    __shared__ __nv_bfloat16 Vs[2][64*ALDK];
    const int tid = threadIdx.x, lane = tid & 31, warp = tid >> 5;
    const int qt = blockIdx.x, h = blockIdx.y, b = blockIdx.z;
    const int t0 = qt * 64;
    const int RS = 3*Cc;

    // Q A-fragments (rope + 1/8 scale already baked in)
    uint32_t qa[4][4];
    {
        int r = t0 + warp*16 + (lane >> 2);
        const __nv_bfloat16* q0 = qkv + (size_t)(b*Tt + r) * RS + h*64;
        const __nv_bfloat16* q8 = q0 + (size_t)8 * RS;
        #pragma unroll
        for (int kk = 0; kk < 4; kk++) {
            int c = kk*16 + (lane & 3)*2;
            qa[kk][0] = *(const uint32_t*)(q0 + c);
            qa[kk][1] = *(const uint32_t*)(q8 + c);
            qa[kk][2] = *(const uint32_t*)(q0 + c + 8);
            qa[kk][3] = *(const uint32_t*)(q8 + c + 8);
        }
    }

    const int krow = tid >> 1, koff = (tid & 1) * 32;
    const __nv_bfloat16* kgbase = qkv + (size_t)(b*Tt + krow) * RS + Cc + h*64 + koff;
    const uint32_t ks0 = (uint32_t)__cvta_generic_to_shared(&Ks[0][0]) + (uint32_t)(krow*ALDK + koff)*2u;
    const uint32_t vs0 = (uint32_t)__cvta_generic_to_shared(&Vs[0][0]) + (uint32_t)(krow*ALDK + koff)*2u;
    const uint32_t KV_STG = 64u*ALDK*2u;

    auto issue = [&](int jt, int stg) {
        const __nv_bfloat16* kp = kgbase + (size_t)jt * 64 * RS;
        const __nv_bfloat16* vp = kp + Cc;
        uint32_t ka = ks0 + (uint32_t)stg * KV_STG;
        uint32_t va = vs0 + (uint32_t)stg * KV_STG;
        #pragma unroll
        for (int i = 0; i < 4; i++) {
            cp_async16(ka + i*16u, kp + i*8);
            cp_async16(va + i*16u, vp + i*8);
        }
        cp_commit();
    };

    float s[8][4], ov[8][4];
    float mrun[2] = {-1e30f, -1e30f}, lrun[2] = {0.f, 0.f};
    #pragma unroll
    for (int nt = 0; nt < 8; nt++)
        #pragma unroll
        for (int e = 0; e < 4; e++) ov[nt][e] = 0.f;

    const uint32_t kbL = (uint32_t)__cvta_generic_to_shared(&Ks[0][0]);
    const uint32_t vbL = (uint32_t)__cvta_generic_to_shared(&Vs[0][0]);
    // per-lane ldsm offsets
    const uint32_t kofs = (uint32_t)(((lane & 7) + ((lane >> 4) << 3)) * ALDK + (((lane >> 3) & 1) << 3)) * 2u;
    const uint32_t vofs = (uint32_t)((lane & 15) * ALDK + ((lane >> 4) << 3)) * 2u;

    issue(0, 0);
    for (int jt = 0; jt <= qt; jt++) {
        cp_wait0();
        __syncthreads();
        if (jt < qt) issue(jt + 1, (jt + 1) & 1);
        int stg = jt & 1;

        // S = Q K^T
        #pragma unroll
        for (int nt = 0; nt < 8; nt++)
            #pragma unroll
            for (int e = 0; e < 4; e++) s[nt][e] = 0.f;
        uint32_t kb = kbL + (uint32_t)stg * KV_STG + kofs;
        #pragma unroll
        for (int kk = 0; kk < 4; kk++) {
            #pragma unroll
            for (int p = 0; p < 4; p++) {
                uint32_t r0, r1, r2, r3;
                ldsm_x4(r0, r1, r2, r3, kb + (uint32_t)(p*16*ALDK + kk*16)*2u);
                mma16816(s[2*p],   qa[kk], r0, r1);
                mma16816(s[2*p+1], qa[kk], r2, r3);
            }
        }

        // online softmax
        bool diag = (jt == qt);
        #pragma unroll
        for (int half = 0; half < 2; half++) {
            int grow = t0 + warp*16 + (lane >> 2) + half*8;
            float mx = mrun[half];
            #pragma unroll
            for (int nt = 0; nt < 8; nt++) {
                float v0 = s[nt][half*2], v1 = s[nt][half*2+1];
                if (diag) {
                    int c0 = jt*64 + nt*8 + (lane & 3)*2;
                    if (c0     > grow) v0 = -1e30f;
                    if (c0 + 1 > grow) v1 = -1e30f;
                    s[nt][half*2] = v0; s[nt][half*2+1] = v1;
                }
                mx = fmaxf(mx, fmaxf(v0, v1));
            }
            mx = fmaxf(mx, __shfl_xor_sync(0xffffffffu, mx, 1));
            mx = fmaxf(mx, __shfl_xor_sync(0xffffffffu, mx, 2));
            float corr = __expf(mrun[half] - mx);
            mrun[half] = mx;
            float ls = 0.f;
            #pragma unroll
            for (int nt = 0; nt < 8; nt++) {
                float p0 = __expf(s[nt][half*2]   - mx);
                float p1 = __expf(s[nt][half*2+1] - mx);
                s[nt][half*2] = p0; s[nt][half*2+1] = p1;
                ls += p0 + p1;
            }
            ls += __shfl_xor_sync(0xffffffffu, ls, 1);
            ls += __shfl_xor_sync(0xffffffffu, ls, 2);
            lrun[half] = lrun[half]*corr + ls;
            #pragma unroll
            for (int nt = 0; nt < 8; nt++) { ov[nt][half*2] *= corr; ov[nt][half*2+1] *= corr; }
        }

        // P (bf16 from S accum frags) @ V
        uint32_t pa[4][4];
        #pragma unroll
        for (int kk = 0; kk < 4; kk++) {
            pa[kk][0] = pack2(s[2*kk][0],   s[2*kk][1]);
            pa[kk][1] = pack2(s[2*kk][2],   s[2*kk][3]);
            pa[kk][2] = pack2(s[2*kk+1][0], s[2*kk+1][1]);
            pa[kk][3] = pack2(s[2*kk+1][2], s[2*kk+1][3]);
        }
        uint32_t vb = vbL + (uint32_t)stg * KV_STG + vofs;
        #pragma unroll
        for (int kk = 0; kk < 4; kk++) {
            #pragma unroll
            for (int p = 0; p < 4; p++) {
                uint32_t r0, r1, r2, r3;
                ldsm_x4_t(r0, r1, r2, r3, vb + (uint32_t)(kk*16*ALDK + p*16)*2u);
                mma16816(ov[2*p],   pa[kk], r0, r1);
                mma16816(ov[2*p+1], pa[kk], r2, r3);
            }
        }
    }

    // write o (bf16)
    #pragma unroll
    for (int half = 0; half < 2; half++) {
        int grow = t0 + warp*16 + (lane >> 2) + half*8;
        float inv = 1.0f / lrun[half];
        __nv_bfloat16* op = o + (size_t)(b*Tt + grow)*Cc + h*64;
        #pragma unroll
        for (int nt = 0; nt < 8; nt++) {
            int c = nt*8 + (lane & 3)*2;
            *(__nv_bfloat162*)(op + c) =
                __floats2bfloat162_rn(ov[nt][half*2]*inv, ov[nt][half*2+1]*inv);
        }
    }
}

// ---------------- launch --------------------------------------------------------
extern "C" void kernel_launch(void* const* d_in, const int* in_sizes, int n_in,
                              void* d_out, int out_size)
{
    (void)in_sizes; (void)n_in; (void)out_size;
    const float* x      = (const float*)d_in[0];
    const float* ln1    = (const float*)d_in[2];
    const float* w_qkv  = (const float*)d_in[3];
    const float* b_qkv  = (const float*)d_in[4];
    const float* a_qkv  = (const float*)d_in[5];
    const float* w_ao   = (const float*)d_in[6];
    const float* b_ao   = (const float*)d_in[7];
    const float* a_ao   = (const float*)d_in[8];
    const float* ln2    = (const float*)d_in[9];
    const float* w_fc   = (const float*)d_in[10];
    const float* b_fc   = (const float*)d_in[11];
    const float* a_fc   = (const float*)d_in[12];
    const float* w_gate = (const float*)d_in[13];
    const float* b_gate = (const float*)d_in[14];
    const float* a_gate = (const float*)d_in[15];
    const float* w_proj = (const float*)d_in[16];
    const float* b_proj = (const float*)d_in[17];
    const float* a_proj = (const float*)d_in[18];
    float* out = (float*)d_out;

    float *x1, *rn, *cn, *part, *ropetab;
    __nv_bfloat16 *qkvb, *h, *o, *h2, *gate, *u, *wq, *wao, *wfc, *wg, *wp;
    cudaGetSymbolAddress((void**)&x1,     g_x1);
    cudaGetSymbolAddress((void**)&rn,     g_rn);
    cudaGetSymbolAddress((void**)&cn,     g_cn);
    cudaGetSymbolAddress((void**)&part,   g_part);
    cudaGetSymbolAddress((void**)&ropetab,g_rope);
    cudaGetSymbolAddress((void**)&qkvb,   g_qkvb);
    cudaGetSymbolAddress((void**)&h,      g_h);
    cudaGetSymbolAddress((void**)&o,      g_o);
    cudaGetSymbolAddress((void**)&h2,     g_h2);
    cudaGetSymbolAddress((void**)&gate,   g_gate);
    cudaGetSymbolAddress((void**)&u,      g_u);
    cudaGetSymbolAddress((void**)&wq,     g_wq);
    cudaGetSymbolAddress((void**)&wao,    g_wao);
    cudaGetSymbolAddress((void**)&wfc,    g_wfc);
    cudaGetSymbolAddress((void**)&wg,     g_wg);
    cudaGetSymbolAddress((void**)&wp,     g_wp);

    const int GSMEM = GSTAGES * (128*GLDA + 32*GLDB) * (int)sizeof(__nv_bfloat16);
    cudaFuncSetAttribute(gemm_yat_mma<0, __nv_bfloat16, float>,
                         cudaFuncAttributeMaxDynamicSharedMemorySize, GSMEM);
    cudaFuncSetAttribute(gemm_yat_mma<1, float, float>,
                         cudaFuncAttributeMaxDynamicSharedMemorySize, GSMEM);
    cudaFuncSetAttribute(gemm_yat_mma<2, __nv_bfloat16, __nv_bfloat16>,
                         cudaFuncAttributeMaxDynamicSharedMemorySize, GSMEM);
    cudaFuncSetAttribute(gemm_yat_mma<3, __nv_bfloat16, float>,
                         cudaFuncAttributeMaxDynamicSharedMemorySize, GSMEM);

    // 0. rope table
    rope_tab<<<Tt*64/256, 256>>>(ropetab);

    // 1. LN1 -> h (bf16), rn
    ln_kernel<<<Mrows, 256>>>(x, ln1, h, rn);

    // 2. qkv = rope(yat(h @ w_qkv)) bf16, q pre-scaled by 1/8
    wconv<<<dim3(3*Cc/256, Cc/64), 256>>>(w_qkv, wq, part, 3*Cc);
    colreduce<<<3*Cc/256, 256>>>(part, cn, 3*Cc, Cc/64);
    gemm_yat_mma<3, __nv_bfloat16, float><<<dim3(3*Cc/128, Mrows/128), 256, GSMEM>>>(
        h, wq, qkvb, rn, cn, b_qkv, a_qkv, ropetab, Mrows, 3*Cc, Cc);

    // 3. attention -> o (bf16)
    flash_attn_mma<<<dim3(Tt/64, Hh, Bb), 128>>>(qkvb, o);

    // 4. x1 = x + yat(o @ w_ao)
    rownorm_bf16<<<Mrows, 256>>>(o, rn, Cc);
    wconv<<<dim3(Cc/256, Cc/64), 256>>>(w_ao, wao, part, Cc);
    colreduce<<<Cc/256, 256>>>(part, cn, Cc, Cc/64);
    gemm_yat_mma<1, float, float><<<dim3(Cc/128, Mrows/128), 256, GSMEM>>>(
        o, wao, x1, rn, cn, b_ao, a_ao, x, Mrows, Cc, Cc);

    // 5. LN2 -> h2 (bf16), rn
    ln_kernel<<<Mrows, 256>>>(x1, ln2, h2, rn);

    // 6. gate = yat(h2 @ w_fc) bf16
    wconv<<<dim3(HID/256, Cc/64), 256>>>(w_fc, wfc, part, HID);
    colreduce<<<HID/256, 256>>>(part, cn, HID, Cc/64);
    gemm_yat_mma<0, __nv_bfloat16, float><<<dim3(HID/128, Mrows/128), 256, GSMEM>>>(
        h2, wfc, gate, rn, cn, b_fc, a_fc, (const float*)nullptr, Mrows, HID, Cc);

    // 7. u = gelu(yat(h2 @ w_gate)) * gate bf16
    wconv<<<dim3(HID/256, Cc/64), 256>>>(w_gate, wg, part, HID);
    colreduce<<<HID/256, 256>>>(part, cn, HID, Cc/64);
    gemm_yat_mma<2, __nv_bfloat16, __nv_bfloat16><<<dim3(HID/128, Mrows/128), 256, GSMEM>>>(
        h2, wg, u, rn, cn, b_gate, a_gate, gate, Mrows, HID, Cc);

    // 8. out = x1 + yat(u @ w_proj)
    rownorm_bf16<<<Mrows, 256>>>(u, rn, HID);
    wconv<<<dim3(Cc/256, HID/64), 256>>>(w_proj, wp, part, Cc);
    colreduce<<<Cc/256, 256>>>(part, cn, Cc, HID/64);
    gemm_yat_mma<1, float, float><<<dim3(Cc/128, Mrows/128), 256, GSMEM>>>(
        u, wp, out, rn, cn, b_proj, a_proj, x1, Mrows, Cc, HID);
}